// round 16
// baseline (speedup 1.0000x reference)
#include <cuda_runtime.h>
#include <cstdint>

#define D1 784
#define G1 196   // D1/4
#define N1 128
#define D2 128
#define G2 32
#define N2 64
#define D3 64
#define G3 16
#define N3 10
#define MT 32    // tokens per block (2 independent halves of 16)
#define NT 256
#define NPART 256
#define KC 25          // k32 chunks for layer1 (800 = 25*32, padded from 784)
#define XROW 204       // ints per token row in smem (816 B, conflict-free ldmatrix)
#define NTILES 16      // n8 tiles in N1=128

// Layer-1 weights prepacked in EXACT m16n8k32 B-fragment order:
// [kc][ntile][lane] -> int2 {b0,b1}
__device__ __align__(16) int g_wq1frag[KC * NTILES * 32 * 2];
__device__ __align__(16) int g_wq2[G2 * N2];   // [kgroup][j]
__device__ __align__(16) int g_wq3[N3 * G3];   // [j][kgroup]
__device__ float g_part1[NPART], g_part2[NPART], g_part3[NPART];
__device__ float g_sw[3];   // 1/clip(mean|w|,1e-5)
__device__ float g_dq[3];   // clip(mean|w|,1e-5)

__device__ __forceinline__ int qw(float w, float s) {
    int q = __float2int_rn(w * s);
    return max(-1, min(1, q));
}
// round-to-nearest-even + saturate to s8, pack 4 -> int (byte0 = v0)
__device__ __forceinline__ int pack_s8x4(float x0, float x1, float x2, float x3) {
    int v0 = __float2int_rn(x0), v1 = __float2int_rn(x1);
    int v2 = __float2int_rn(x2), v3 = __float2int_rn(x3);
    int r;
    asm("cvt.pack.sat.s8.s32.b32 %0, %1, %2, %3;" : "=r"(r) : "r"(v3), "r"(v2), "r"(0));
    asm("cvt.pack.sat.s8.s32.b32 %0, %1, %2, %0;" : "+r"(r) : "r"(v1), "r"(v0));
    return r;
}
__device__ __forceinline__ uint32_t smem_u32(const void* p) {
    return (uint32_t)__cvta_generic_to_shared(p);
}
__device__ __forceinline__ void ldsm_x4(uint32_t addr, int& r0, int& r1, int& r2, int& r3) {
    asm volatile("ldmatrix.sync.aligned.m8n8.x4.shared.b16 {%0,%1,%2,%3}, [%4];\n"
                 : "=r"(r0), "=r"(r1), "=r"(r2), "=r"(r3) : "r"(addr));
}
__device__ __forceinline__ void imma16832(int* d, const int* a, const int* b) {
    asm volatile("mma.sync.aligned.m16n8k32.row.col.s32.s8.s8.s32 "
                 "{%0,%1,%2,%3}, {%4,%5,%6,%7}, {%8,%9}, {%0,%1,%2,%3};\n"
                 : "+r"(d[0]), "+r"(d[1]), "+r"(d[2]), "+r"(d[3])
                 : "r"(a[0]), "r"(a[1]), "r"(a[2]), "r"(a[3]), "r"(b[0]), "r"(b[1]));
}

// ---------------- prep: deterministic mean(|w|) partials ----------------
__global__ void prep_partial(const float* __restrict__ w1,
                             const float* __restrict__ w2,
                             const float* __restrict__ w3) {
    __shared__ float red[NT];
    int t = threadIdx.x;
    int gid = blockIdx.x * NT + t;
    int stride = NPART * NT;
    float s1 = 0.f, s2 = 0.f, s3 = 0.f;
    for (int i = gid; i < N1 * D1; i += stride) s1 += fabsf(w1[i]);
    for (int i = gid; i < N2 * D2; i += stride) s2 += fabsf(w2[i]);
    for (int i = gid; i < N3 * D3; i += stride) s3 += fabsf(w3[i]);

    red[t] = s1; __syncthreads();
    for (int s = NT / 2; s > 0; s >>= 1) { if (t < s) red[t] += red[t + s]; __syncthreads(); }
    if (t == 0) g_part1[blockIdx.x] = red[0];
    __syncthreads();
    red[t] = s2; __syncthreads();
    for (int s = NT / 2; s > 0; s >>= 1) { if (t < s) red[t] += red[t + s]; __syncthreads(); }
    if (t == 0) g_part2[blockIdx.x] = red[0];
    __syncthreads();
    red[t] = s3; __syncthreads();
    for (int s = NT / 2; s > 0; s >>= 1) { if (t < s) red[t] += red[t + s]; __syncthreads(); }
    if (t == 0) g_part3[blockIdx.x] = red[0];
}

// ---------------- prep: finalize means, quantize w2/w3 ----------------
__global__ void prep_finalize(const float* __restrict__ w2,
                              const float* __restrict__ w3) {
    __shared__ float red[NT];
    __shared__ float s_sw2, s_sw3;
    int t = threadIdx.x;

    red[t] = g_part1[t]; __syncthreads();
    for (int s = NT / 2; s > 0; s >>= 1) { if (t < s) red[t] += red[t + s]; __syncthreads(); }
    if (t == 0) {
        float c = fmaxf(red[0] / (float)(N1 * D1), 1e-5f);
        float sw = 1.0f / c; g_sw[0] = sw; g_dq[0] = 1.0f / sw;
    }
    __syncthreads();
    red[t] = g_part2[t]; __syncthreads();
    for (int s = NT / 2; s > 0; s >>= 1) { if (t < s) red[t] += red[t + s]; __syncthreads(); }
    if (t == 0) {
        float c = fmaxf(red[0] / (float)(N2 * D2), 1e-5f);
        float sw = 1.0f / c; g_sw[1] = sw; g_dq[1] = 1.0f / sw; s_sw2 = sw;
    }
    __syncthreads();
    red[t] = g_part3[t]; __syncthreads();
    for (int s = NT / 2; s > 0; s >>= 1) { if (t < s) red[t] += red[t + s]; __syncthreads(); }
    if (t == 0) {
        float c = fmaxf(red[0] / (float)(N3 * D3), 1e-5f);
        float sw = 1.0f / c; g_sw[2] = sw; g_dq[2] = 1.0f / sw; s_sw3 = sw;
    }
    __syncthreads();

    float sw2 = s_sw2, sw3 = s_sw3;
    for (int idx = t; idx < G2 * N2; idx += NT) {
        int g = idx / N2, j = idx % N2;
        const float* wp = w2 + j * D2 + 4 * g;
        int p = (qw(wp[0], sw2) & 0xff)
              | ((qw(wp[1], sw2) & 0xff) << 8)
              | ((qw(wp[2], sw2) & 0xff) << 16)
              | ((qw(wp[3], sw2) & 0xff) << 24);
        g_wq2[idx] = p;
    }
    for (int idx = t; idx < N3 * G3; idx += NT) {
        int j = idx / G3, g = idx % G3;
        const float* wp = w3 + j * D3 + 4 * g;
        int p = (qw(wp[0], sw3) & 0xff)
              | ((qw(wp[1], sw3) & 0xff) << 8)
              | ((qw(wp[2], sw3) & 0xff) << 16)
              | ((qw(wp[3], sw3) & 0xff) << 24);
        g_wq3[idx] = p;
    }
}

// ---------------- prep: quantize w1 into IMMA B-fragment order ----------------
__global__ void prep_quant_w1(const float* __restrict__ w1) {
    int idx = blockIdx.x * NT + threadIdx.x;     // one int per thread
    if (idx >= KC * NTILES * 32 * 2) return;
    float sw = g_sw[0];
    int kc   = idx >> 10;             // 1024 ints per k-chunk
    int rem  = idx & 1023;
    int nt   = rem >> 6;              // n-tile (16 per chunk)
    int lane = (rem >> 1) & 31;
    int r    = idx & 1;               // b0 / b1
    int n    = nt * 8 + (lane >> 2);
    int k0   = kc * 32 + r * 16 + (lane & 3) * 4;
    int p = 0;
    #pragma unroll
    for (int b = 0; b < 4; b++) {
        int k = k0 + b;
        int q = (k < D1) ? qw(w1[n * D1 + k], sw) : 0;
        p |= (q & 0xff) << (8 * b);
    }
    g_wq1frag[idx] = p;
}

// half-scoped barrier: 128 threads, named barrier 1 or 2
#define BARH() asm volatile("bar.sync %0, 128;" :: "r"(half + 1) : "memory")

// ---------------- fused main kernel ----------------
__global__ __launch_bounds__(NT, 5) void ffn_main(
    const float* __restrict__ x,
    const float* __restrict__ sc1,
    const float* __restrict__ sc2,
    const float* __restrict__ sc3,
    float* __restrict__ out)
{
    // Region A: xq [32][204] ints; per half reused as h1 f32 [16][132] within
    // that half's own 16*816B sub-region (no cross-half aliasing).
    __shared__ __align__(16) char s_regionA[MT * XROW * 4];
    __shared__ float s_scale1[D1];
    __shared__ float s_scale2[D2];
    __shared__ float s_scale3[D3];
    __shared__ __align__(16) int s_h1qT[G2 * 34];   // [kgroup][token] (disjoint cols per half)
    __shared__ __align__(16) int s_h2q[MT * G3];
    __shared__ float s_c1[MT], s_c2[MT], s_c3[MT];

    int* s_xq = (int*)s_regionA;                 // [tok][XROW]

    const int t = threadIdx.x;
    const int warp = t >> 5, lane = t & 31;
    const int half = warp >> 2;        // 0 or 1: independent 128-thread pipeline
    const int th = t & 127;            // thread-in-half
    const int wh = warp & 3;           // warp-in-half
    float* s_h1h = (float*)(s_regionA + half * 16 * XROW * 4);  // [l][132], l=0..15
    const float dq1 = g_dq[0], dq2 = g_dq[1], dq3 = g_dq[2];

    // each half redundantly loads the full scale tables (identical values)
    for (int i = th; i < D1; i += 128) s_scale1[i] = sc1[i];
    if (th < D2) s_scale2[th] = sc2[th];
    if (th < D3) s_scale3[th] = sc3[th];
    // zero the k-padding ints (f = 196..203) of this half's 16 token rows
    {
        int tokl = th >> 3, f = G1 + (th & 7);
        s_xq[(half * 16 + tokl) * XROW + f] = 0;
    }
    BARH();

    // ---- phase 1: per-token RMSNorm + int8 absmax quant of x ----
    // Merged reduction: ssq and m = max|sv*x| in ONE shuffle chain;
    // amx = m * rden (== elementwise max of |sv*(x*rden)| up to 1 ulp).
    #pragma unroll 1
    for (int c = 0; c < 4; c++) {
        int ltok = half * 16 + wh * 4 + c;
        const float4* xr = (const float4*)(x + (size_t)(blockIdx.x * MT + ltok) * D1);
        float4 xv[7];
        float ssq = 0.f, mm = 0.f;
        #pragma unroll
        for (int i = 0; i < 7; i++) {
            int f = lane + 32 * i;
            xv[i] = make_float4(0.f, 0.f, 0.f, 0.f);
            if (f < G1) {
                float4 v = xr[f];
                float4 sv = *(const float4*)(&s_scale1[4 * f]);
                xv[i] = v;
                ssq += v.x * v.x + v.y * v.y + v.z * v.z + v.w * v.w;
                mm = fmaxf(mm, fmaxf(fmaxf(fabsf(sv.x * v.x), fabsf(sv.y * v.y)),
                                     fmaxf(fabsf(sv.z * v.z), fabsf(sv.w * v.w))));
            }
        }
        #pragma unroll
        for (int m = 16; m > 0; m >>= 1) {
            ssq += __shfl_xor_sync(0xffffffffu, ssq, m);
            mm = fmaxf(mm, __shfl_xor_sync(0xffffffffu, mm, m));
        }
        float denom = sqrtf(ssq) * (1.0f / 28.0f) + 1e-8f;
        float rden = 1.0f / denom;
        float amx = mm * rden;
        float amc = fmaxf(amx, 1e-5f);
        float s = 127.0f / amc;
        if (lane == 0) s_c1[ltok] = (1.0f / s) * dq1;
        #pragma unroll
        for (int i = 0; i < 7; i++) {
            int f = lane + 32 * i;
            if (f < G1) {
                float4 sv = *(const float4*)(&s_scale1[4 * f]);
                float4 y;
                y.x = sv.x * (xv[i].x * rden);
                y.y = sv.y * (xv[i].y * rden);
                y.z = sv.z * (xv[i].z * rden);
                y.w = sv.w * (xv[i].w * rden);
                s_xq[ltok * XROW + f] = pack_s8x4(y.x * s, y.y * s, y.z * s, y.w * s);
            }
        }
    }
    BARH();   // this half's xq complete before its warps ldmatrix it

    // ---- GEMM1: this half's [16 x 128] IMMA; in-loop A (ldsm) + B (LDG) ----
    int acc[4][4];
    #pragma unroll
    for (int i = 0; i < 4; i++)
        #pragma unroll
        for (int j = 0; j < 4; j++) acc[i][j] = 0;

    // A ldmatrix lane addressing (m-tile = this half's 16 rows)
    const int gA = lane >> 3, iA = lane & 7;
    const int a_row = half * 16 + (((gA == 1) || (gA == 3)) ? 8 : 0) + iA;
    const uint32_t a_base = smem_u32(s_xq + a_row * XROW) + ((gA >= 2) ? 16u : 0u);
    // B fragments: this warp's first n-tile = wh*4
    const int2* bfr = ((const int2*)g_wq1frag) + (wh * 4) * 32 + lane;

    #pragma unroll 5
    for (int kc = 0; kc < KC; kc++) {
        int a[4];
        ldsm_x4(a_base + (uint32_t)kc * 32u, a[0], a[1], a[2], a[3]);
        const int2* bk = bfr + kc * (NTILES * 32);
        int2 b0 = __ldg(bk);
        int2 b1 = __ldg(bk + 32);
        int2 b2 = __ldg(bk + 64);
        int2 b3 = __ldg(bk + 96);
        imma16832(acc[0], a, (const int*)&b0);
        imma16832(acc[1], a, (const int*)&b1);
        imma16832(acc[2], a, (const int*)&b2);
        imma16832(acc[3], a, (const int*)&b3);
    }
    BARH();   // this half's ldmatrix reads done; safe to reuse its xq region

    // scatter relu(acc * c1) as f32 into this half's h1 [l][132]
    {
        int l_lo = lane >> 2;                       // local row 0..7
        float c1lo = s_c1[half * 16 + l_lo];
        float c1hi = s_c1[half * 16 + l_lo + 8];
        #pragma unroll
        for (int nt = 0; nt < 4; nt++) {
            int j = wh * 32 + nt * 8 + 2 * (lane & 3);
            float2 vlo, vhi;
            vlo.x = fmaxf((float)acc[nt][0] * c1lo, 0.f);
            vlo.y = fmaxf((float)acc[nt][1] * c1lo, 0.f);
            vhi.x = fmaxf((float)acc[nt][2] * c1hi, 0.f);
            vhi.y = fmaxf((float)acc[nt][3] * c1hi, 0.f);
            *(float2*)&s_h1h[l_lo * 132 + j] = vlo;
            *(float2*)&s_h1h[(l_lo + 8) * 132 + j] = vhi;
        }
    }
    BARH();

    // ---- epilogue 1: RMSNorm(128) + quant (merged reduction) ----
    #pragma unroll 1
    for (int c = 0; c < 4; c++) {
        int l = wh * 4 + c;
        int tok = half * 16 + l;
        float4 hv = *(const float4*)&s_h1h[l * 132 + 4 * lane];
        float4 sv = *(const float4*)&s_scale2[4 * lane];
        float ssq = hv.x * hv.x + hv.y * hv.y + hv.z * hv.z + hv.w * hv.w;
        float mm = fmaxf(fmaxf(fabsf(sv.x * hv.x), fabsf(sv.y * hv.y)),
                         fmaxf(fabsf(sv.z * hv.z), fabsf(sv.w * hv.w)));
        #pragma unroll
        for (int m = 16; m > 0; m >>= 1) {
            ssq += __shfl_xor_sync(0xffffffffu, ssq, m);
            mm = fmaxf(mm, __shfl_xor_sync(0xffffffffu, mm, m));
        }
        float denom = sqrtf(ssq) * 0.08838834764831845f + 1e-8f;
        float rden = 1.0f / denom;
        float amx = mm * rden;
        float amc = fmaxf(amx, 1e-5f);
        float s = 127.0f / amc;
        if (lane == 0) s_c2[tok] = (1.0f / s) * dq2;
        float4 y;
        y.x = sv.x * (hv.x * rden);
        y.y = sv.y * (hv.y * rden);
        y.z = sv.z * (hv.z * rden);
        y.w = sv.w * (hv.w * rden);
        s_h1qT[lane * 34 + tok] = pack_s8x4(y.x * s, y.y * s, y.z * s, y.w * s);
    }
    BARH();

    // ---- GEMM2: this half's [16 x 64] dp4a (weights via L1/L2) ----
    const int tj2 = th & 15;
    const int j2 = tj2 * 4;
    const int tm2 = th >> 4;        // 0..7 -> token pair within half
    const int tok0 = half * 16 + tm2 * 2;
    int acc2[2][4];
    #pragma unroll
    for (int c = 0; c < 2; c++)
        #pragma unroll
        for (int j = 0; j < 4; j++) acc2[c][j] = 0;

    #pragma unroll 8
    for (int g = 0; g < G2; g++) {
        int2 a = *(const int2*)&s_h1qT[g * 34 + tok0];
        int4 w = *(const int4*)(g_wq2 + g * N2 + j2);
        acc2[0][0] = __dp4a(a.x, w.x, acc2[0][0]); acc2[0][1] = __dp4a(a.x, w.y, acc2[0][1]);
        acc2[0][2] = __dp4a(a.x, w.z, acc2[0][2]); acc2[0][3] = __dp4a(a.x, w.w, acc2[0][3]);
        acc2[1][0] = __dp4a(a.y, w.x, acc2[1][0]); acc2[1][1] = __dp4a(a.y, w.y, acc2[1][1]);
        acc2[1][2] = __dp4a(a.y, w.z, acc2[1][2]); acc2[1][3] = __dp4a(a.y, w.w, acc2[1][3]);
    }

    // ---- epilogue 2: RMSNorm(64) + quant (merged 4-step reduction) ----
    #pragma unroll
    for (int c = 0; c < 2; c++) {
        int tok = tok0 + c;
        float cf = s_c2[tok];
        float h[4];
        float ssq = 0.f, mm = 0.f;
        #pragma unroll
        for (int j = 0; j < 4; j++) {
            float v = fmaxf((float)acc2[c][j] * cf, 0.f);
            h[j] = v;
            ssq += v * v;
            mm = fmaxf(mm, fabsf(s_scale3[j2 + j] * v));
        }
        #pragma unroll
        for (int m = 1; m < 16; m <<= 1) {
            ssq += __shfl_xor_sync(0xffffffffu, ssq, m);
            mm = fmaxf(mm, __shfl_xor_sync(0xffffffffu, mm, m));
        }
        float denom = sqrtf(ssq) * 0.125f + 1e-8f;
        float rden = 1.0f / denom;
        float amx = mm * rden;
        float amc = fmaxf(amx, 1e-5f);
        float s = 127.0f / amc;
        if (tj2 == 0) s_c3[tok] = (1.0f / s) * dq3;
        float y0 = s_scale3[j2 + 0] * (h[0] * rden);
        float y1 = s_scale3[j2 + 1] * (h[1] * rden);
        float y2 = s_scale3[j2 + 2] * (h[2] * rden);
        float y3 = s_scale3[j2 + 3] * (h[3] * rden);
        s_h2q[tok * G3 + tj2] = pack_s8x4(y0 * s, y1 * s, y2 * s, y3 * s);
    }
    BARH();

    // ---- GEMM3: this half's [16 x 10], write output ----
    for (int p = th; p < 16 * N3; p += 128) {
        int l = p / N3, j = p % N3;
        int ltok = half * 16 + l;
        int a3 = 0;
        #pragma unroll
        for (int g = 0; g < G3; g++)
            a3 = __dp4a(s_h2q[ltok * G3 + g], g_wq3[j * G3 + g], a3);
        out[(blockIdx.x * MT + ltok) * N3 + j] = (float)a3 * s_c3[ltok];
    }
}

extern "C" void kernel_launch(void* const* d_in, const int* in_sizes, int n_in,
                              void* d_out, int out_size) {
    const float* x   = (const float*)d_in[0];
    const float* w1  = (const float*)d_in[1];
    const float* sc1 = (const float*)d_in[2];
    const float* w2  = (const float*)d_in[3];
    const float* sc2 = (const float*)d_in[4];
    const float* w3  = (const float*)d_in[5];
    const float* sc3 = (const float*)d_in[6];
    float* out = (float*)d_out;

    int ntok = in_sizes[0] / D1;   // 65536

    prep_partial<<<NPART, NT>>>(w1, w2, w3);
    prep_finalize<<<1, NT>>>(w2, w3);
    prep_quant_w1<<<(KC * NTILES * 32 * 2 + NT - 1) / NT, NT>>>(w1);
    ffn_main<<<ntok / MT, NT>>>(x, sc1, sc2, sc3, out);
}

// round 17
// speedup vs baseline: 1.0827x; 1.0827x over previous
#include <cuda_runtime.h>
#include <cstdint>

#define D1 784
#define G1 196   // D1/4
#define N1 128
#define D2 128
#define G2 32
#define N2 64
#define D3 64
#define G3 16
#define N3 10
#define MT 32    // tokens per block (2 independent halves of 16)
#define NT 256
#define NPART 256
#define KC 25          // k32 chunks for layer1 (800 = 25*32, padded from 784)
#define XROW 204       // ints per token row in smem (816 B, conflict-free ldmatrix)
#define NTILES 16      // n8 tiles in N1=128

// Layer-1 weights prepacked in EXACT m16n8k32 B-fragment order:
// [kc][ntile][lane] -> int2 {b0,b1}
__device__ __align__(16) int g_wq1frag[KC * NTILES * 32 * 2];
__device__ __align__(16) int g_wq2[G2 * N2];   // [kgroup][j]
__device__ __align__(16) int g_wq3[N3 * G3];   // [j][kgroup]
__device__ float g_part1[NPART], g_part2[NPART], g_part3[NPART];
__device__ float g_sw[3];   // 1/clip(mean|w|,1e-5)
__device__ float g_dq[3];   // clip(mean|w|,1e-5)

__device__ __forceinline__ int qw(float w, float s) {
    int q = __float2int_rn(w * s);
    return max(-1, min(1, q));
}
// round-to-nearest-even + saturate to s8, pack 4 -> int (byte0 = v0)
__device__ __forceinline__ int pack_s8x4(float x0, float x1, float x2, float x3) {
    int v0 = __float2int_rn(x0), v1 = __float2int_rn(x1);
    int v2 = __float2int_rn(x2), v3 = __float2int_rn(x3);
    int r;
    asm("cvt.pack.sat.s8.s32.b32 %0, %1, %2, %3;" : "=r"(r) : "r"(v3), "r"(v2), "r"(0));
    asm("cvt.pack.sat.s8.s32.b32 %0, %1, %2, %0;" : "+r"(r) : "r"(v1), "r"(v0));
    return r;
}
// pack 2 -> u16 (byte0 = x0)
__device__ __forceinline__ short pack_s8x2(float x0, float x1) {
    int v0 = __float2int_rn(x0), v1 = __float2int_rn(x1);
    int r;
    asm("cvt.pack.sat.s8.s32.b32 %0, %1, %2, %3;" : "=r"(r) : "r"(v1), "r"(v0), "r"(0));
    return (short)r;
}
__device__ __forceinline__ uint32_t smem_u32(const void* p) {
    return (uint32_t)__cvta_generic_to_shared(p);
}
__device__ __forceinline__ void ldsm_x4(uint32_t addr, int& r0, int& r1, int& r2, int& r3) {
    asm volatile("ldmatrix.sync.aligned.m8n8.x4.shared.b16 {%0,%1,%2,%3}, [%4];\n"
                 : "=r"(r0), "=r"(r1), "=r"(r2), "=r"(r3) : "r"(addr));
}
__device__ __forceinline__ void imma16832(int* d, const int* a, const int* b) {
    asm volatile("mma.sync.aligned.m16n8k32.row.col.s32.s8.s8.s32 "
                 "{%0,%1,%2,%3}, {%4,%5,%6,%7}, {%8,%9}, {%0,%1,%2,%3};\n"
                 : "+r"(d[0]), "+r"(d[1]), "+r"(d[2]), "+r"(d[3])
                 : "r"(a[0]), "r"(a[1]), "r"(a[2]), "r"(a[3]), "r"(b[0]), "r"(b[1]));
}

// ---------------- prep: deterministic mean(|w|) partials ----------------
__global__ void prep_partial(const float* __restrict__ w1,
                             const float* __restrict__ w2,
                             const float* __restrict__ w3) {
    __shared__ float red[NT];
    int t = threadIdx.x;
    int gid = blockIdx.x * NT + t;
    int stride = NPART * NT;
    float s1 = 0.f, s2 = 0.f, s3 = 0.f;
    for (int i = gid; i < N1 * D1; i += stride) s1 += fabsf(w1[i]);
    for (int i = gid; i < N2 * D2; i += stride) s2 += fabsf(w2[i]);
    for (int i = gid; i < N3 * D3; i += stride) s3 += fabsf(w3[i]);

    red[t] = s1; __syncthreads();
    for (int s = NT / 2; s > 0; s >>= 1) { if (t < s) red[t] += red[t + s]; __syncthreads(); }
    if (t == 0) g_part1[blockIdx.x] = red[0];
    __syncthreads();
    red[t] = s2; __syncthreads();
    for (int s = NT / 2; s > 0; s >>= 1) { if (t < s) red[t] += red[t + s]; __syncthreads(); }
    if (t == 0) g_part2[blockIdx.x] = red[0];
    __syncthreads();
    red[t] = s3; __syncthreads();
    for (int s = NT / 2; s > 0; s >>= 1) { if (t < s) red[t] += red[t + s]; __syncthreads(); }
    if (t == 0) g_part3[blockIdx.x] = red[0];
}

// ---------------- prep: finalize means, quantize w2/w3 ----------------
__global__ void prep_finalize(const float* __restrict__ w2,
                              const float* __restrict__ w3) {
    __shared__ float red[NT];
    __shared__ float s_sw2, s_sw3;
    int t = threadIdx.x;

    red[t] = g_part1[t]; __syncthreads();
    for (int s = NT / 2; s > 0; s >>= 1) { if (t < s) red[t] += red[t + s]; __syncthreads(); }
    if (t == 0) {
        float c = fmaxf(red[0] / (float)(N1 * D1), 1e-5f);
        float sw = 1.0f / c; g_sw[0] = sw; g_dq[0] = 1.0f / sw;
    }
    __syncthreads();
    red[t] = g_part2[t]; __syncthreads();
    for (int s = NT / 2; s > 0; s >>= 1) { if (t < s) red[t] += red[t + s]; __syncthreads(); }
    if (t == 0) {
        float c = fmaxf(red[0] / (float)(N2 * D2), 1e-5f);
        float sw = 1.0f / c; g_sw[1] = sw; g_dq[1] = 1.0f / sw; s_sw2 = sw;
    }
    __syncthreads();
    red[t] = g_part3[t]; __syncthreads();
    for (int s = NT / 2; s > 0; s >>= 1) { if (t < s) red[t] += red[t + s]; __syncthreads(); }
    if (t == 0) {
        float c = fmaxf(red[0] / (float)(N3 * D3), 1e-5f);
        float sw = 1.0f / c; g_sw[2] = sw; g_dq[2] = 1.0f / sw; s_sw3 = sw;
    }
    __syncthreads();

    float sw2 = s_sw2, sw3 = s_sw3;
    for (int idx = t; idx < G2 * N2; idx += NT) {
        int g = idx / N2, j = idx % N2;
        const float* wp = w2 + j * D2 + 4 * g;
        int p = (qw(wp[0], sw2) & 0xff)
              | ((qw(wp[1], sw2) & 0xff) << 8)
              | ((qw(wp[2], sw2) & 0xff) << 16)
              | ((qw(wp[3], sw2) & 0xff) << 24);
        g_wq2[idx] = p;
    }
    for (int idx = t; idx < N3 * G3; idx += NT) {
        int j = idx / G3, g = idx % G3;
        const float* wp = w3 + j * D3 + 4 * g;
        int p = (qw(wp[0], sw3) & 0xff)
              | ((qw(wp[1], sw3) & 0xff) << 8)
              | ((qw(wp[2], sw3) & 0xff) << 16)
              | ((qw(wp[3], sw3) & 0xff) << 24);
        g_wq3[idx] = p;
    }
}

// ---------------- prep: quantize w1 into IMMA B-fragment order ----------------
__global__ void prep_quant_w1(const float* __restrict__ w1) {
    int idx = blockIdx.x * NT + threadIdx.x;     // one int per thread
    if (idx >= KC * NTILES * 32 * 2) return;
    float sw = g_sw[0];
    int kc   = idx >> 10;             // 1024 ints per k-chunk
    int rem  = idx & 1023;
    int nt   = rem >> 6;              // n-tile (16 per chunk)
    int lane = (rem >> 1) & 31;
    int r    = idx & 1;               // b0 / b1
    int n    = nt * 8 + (lane >> 2);
    int k0   = kc * 32 + r * 16 + (lane & 3) * 4;
    int p = 0;
    #pragma unroll
    for (int b = 0; b < 4; b++) {
        int k = k0 + b;
        int q = (k < D1) ? qw(w1[n * D1 + k], sw) : 0;
        p |= (q & 0xff) << (8 * b);
    }
    g_wq1frag[idx] = p;
}

// half-scoped barrier: 128 threads, named barrier 1 or 2
#define BARH() asm volatile("bar.sync %0, 128;" :: "r"(half + 1) : "memory")

// ---------------- fused main kernel ----------------
__global__ __launch_bounds__(NT, 5) void ffn_main(
    const float* __restrict__ x,
    const float* __restrict__ sc1,
    const float* __restrict__ sc2,
    const float* __restrict__ sc3,
    float* __restrict__ out)
{
    __shared__ __align__(16) char s_regionA[MT * XROW * 4];  // xq [32][204] ints
    __shared__ float s_scale1[D1];
    __shared__ float s_scale2[D2];
    __shared__ float s_scale3[D3];
    __shared__ __align__(16) int s_h1qT[G2 * 34];   // [kgroup][token] (disjoint cols per half)
    __shared__ __align__(16) int s_h2q[MT * G3];
    __shared__ float s_ep1[2 * 16 * 4 * 2];         // [half][row][warp][{ssq,mm}]
    __shared__ float s_c1[MT], s_c2[MT], s_c3[MT];

    int* s_xq = (int*)s_regionA;                 // [tok][XROW]

    const int t = threadIdx.x;
    const int warp = t >> 5, lane = t & 31;
    const int half = warp >> 2;        // 0 or 1: independent 128-thread pipeline
    const int th = t & 127;            // thread-in-half
    const int wh = warp & 3;           // warp-in-half
    const float dq1 = g_dq[0], dq2 = g_dq[1], dq3 = g_dq[2];

    // each half redundantly loads the full scale tables (identical values)
    for (int i = th; i < D1; i += 128) s_scale1[i] = sc1[i];
    if (th < D2) s_scale2[th] = sc2[th];
    if (th < D3) s_scale3[th] = sc3[th];
    // zero the k-padding ints (f = 196..203) of this half's 16 token rows
    {
        int tokl = th >> 3, f = G1 + (th & 7);
        s_xq[(half * 16 + tokl) * XROW + f] = 0;
    }
    BARH();

    // ---- phase 1: per-token RMSNorm + int8 absmax quant of x (R14-identical) ----
    #pragma unroll 1
    for (int c = 0; c < 4; c++) {
        int ltok = half * 16 + wh * 4 + c;
        const float4* xr = (const float4*)(x + (size_t)(blockIdx.x * MT + ltok) * D1);
        float4 xv[7];
        float ssq = 0.f;
        #pragma unroll
        for (int i = 0; i < 7; i++) {
            int f = lane + 32 * i;
            xv[i] = make_float4(0.f, 0.f, 0.f, 0.f);
            if (f < G1) {
                float4 v = xr[f];
                xv[i] = v;
                ssq += v.x * v.x + v.y * v.y + v.z * v.z + v.w * v.w;
            }
        }
        #pragma unroll
        for (int m = 16; m > 0; m >>= 1)
            ssq += __shfl_xor_sync(0xffffffffu, ssq, m);
        float denom = sqrtf(ssq) * (1.0f / 28.0f) + 1e-8f;
        float rden = 1.0f / denom;       // single division per token

        float amx = 0.f;
        #pragma unroll
        for (int i = 0; i < 7; i++) {
            int f = lane + 32 * i;
            if (f < G1) {
                float4 sv = *(const float4*)(&s_scale1[4 * f]);
                float4 y;
                y.x = sv.x * (xv[i].x * rden);
                y.y = sv.y * (xv[i].y * rden);
                y.z = sv.z * (xv[i].z * rden);
                y.w = sv.w * (xv[i].w * rden);
                xv[i] = y;
                amx = fmaxf(amx, fmaxf(fmaxf(fabsf(y.x), fabsf(y.y)),
                                       fmaxf(fabsf(y.z), fabsf(y.w))));
            }
        }
        #pragma unroll
        for (int m = 16; m > 0; m >>= 1)
            amx = fmaxf(amx, __shfl_xor_sync(0xffffffffu, amx, m));
        float amc = fmaxf(amx, 1e-5f);
        float s = 127.0f / amc;
        if (lane == 0) s_c1[ltok] = (1.0f / s) * dq1;
        #pragma unroll
        for (int i = 0; i < 7; i++) {
            int f = lane + 32 * i;
            if (f < G1) {
                float4 y = xv[i];
                s_xq[ltok * XROW + f] = pack_s8x4(y.x * s, y.y * s, y.z * s, y.w * s);
            }
        }
    }
    BARH();   // this half's xq complete before its warps ldmatrix it

    // ---- GEMM1: this half's [16 x 128] IMMA; in-loop A (ldsm) + B (LDG) ----
    int acc[4][4];
    #pragma unroll
    for (int i = 0; i < 4; i++)
        #pragma unroll
        for (int j = 0; j < 4; j++) acc[i][j] = 0;

    const int gA = lane >> 3, iA = lane & 7;
    const int a_row = half * 16 + (((gA == 1) || (gA == 3)) ? 8 : 0) + iA;
    const uint32_t a_base = smem_u32(s_xq + a_row * XROW) + ((gA >= 2) ? 16u : 0u);
    const int2* bfr = ((const int2*)g_wq1frag) + (wh * 4) * 32 + lane;

    #pragma unroll 5
    for (int kc = 0; kc < KC; kc++) {
        int a[4];
        ldsm_x4(a_base + (uint32_t)kc * 32u, a[0], a[1], a[2], a[3]);
        const int2* bk = bfr + kc * (NTILES * 32);
        int2 b0 = __ldg(bk);
        int2 b1 = __ldg(bk + 32);
        int2 b2 = __ldg(bk + 64);
        int2 b3 = __ldg(bk + 96);
        imma16832(acc[0], a, (const int*)&b0);
        imma16832(acc[1], a, (const int*)&b1);
        imma16832(acc[2], a, (const int*)&b2);
        imma16832(acc[3], a, (const int*)&b3);
    }
    // no barrier needed: xq is not overwritten; epilogue is fragment-side.

    // ---- epilogue 1 (fragment-side): RMSNorm(128) + quant, no h1 round-trip ----
    {
        const int rl = lane >> 2;                       // local row 0..7
        const int tokL = half * 16 + rl;
        const int tokH = tokL + 8;
        float c1lo = s_c1[tokL];
        float c1hi = s_c1[tokH];
        float hlo[4][2], hhi[4][2];
        float ssq_lo = 0.f, mm_lo = 0.f, ssq_hi = 0.f, mm_hi = 0.f;
        #pragma unroll
        for (int nt = 0; nt < 4; nt++) {
            int j = wh * 32 + nt * 8 + 2 * (lane & 3);
            float sv0 = s_scale2[j], sv1 = s_scale2[j + 1];
            float a0 = fmaxf((float)acc[nt][0] * c1lo, 0.f);
            float a1 = fmaxf((float)acc[nt][1] * c1lo, 0.f);
            float b0 = fmaxf((float)acc[nt][2] * c1hi, 0.f);
            float b1 = fmaxf((float)acc[nt][3] * c1hi, 0.f);
            hlo[nt][0] = a0; hlo[nt][1] = a1;
            hhi[nt][0] = b0; hhi[nt][1] = b1;
            ssq_lo += a0 * a0 + a1 * a1;
            ssq_hi += b0 * b0 + b1 * b1;
            mm_lo = fmaxf(mm_lo, fmaxf(fabsf(sv0 * a0), fabsf(sv1 * a1)));
            mm_hi = fmaxf(mm_hi, fmaxf(fabsf(sv0 * b0), fabsf(sv1 * b1)));
        }
        #pragma unroll
        for (int m = 1; m < 4; m <<= 1) {
            ssq_lo += __shfl_xor_sync(0xffffffffu, ssq_lo, m);
            mm_lo = fmaxf(mm_lo, __shfl_xor_sync(0xffffffffu, mm_lo, m));
            ssq_hi += __shfl_xor_sync(0xffffffffu, ssq_hi, m);
            mm_hi = fmaxf(mm_hi, __shfl_xor_sync(0xffffffffu, mm_hi, m));
        }
        if ((lane & 3) == 0) {
            s_ep1[(tokL * 4 + wh) * 2 + 0] = ssq_lo;
            s_ep1[(tokL * 4 + wh) * 2 + 1] = mm_lo;
            s_ep1[(tokH * 4 + wh) * 2 + 0] = ssq_hi;
            s_ep1[(tokH * 4 + wh) * 2 + 1] = mm_hi;
        }
        BARH();
        // combine the 4 warp partials for this thread's two rows
        float ssqL = 0.f, mmL = 0.f, ssqH = 0.f, mmH = 0.f;
        #pragma unroll
        for (int w = 0; w < 4; w++) {
            ssqL += s_ep1[(tokL * 4 + w) * 2 + 0];
            mmL = fmaxf(mmL, s_ep1[(tokL * 4 + w) * 2 + 1]);
            ssqH += s_ep1[(tokH * 4 + w) * 2 + 0];
            mmH = fmaxf(mmH, s_ep1[(tokH * 4 + w) * 2 + 1]);
        }
        float rdenL = 1.0f / (sqrtf(ssqL) * 0.08838834764831845f + 1e-8f);
        float sL = 127.0f / fmaxf(mmL * rdenL, 1e-5f);
        float rdenH = 1.0f / (sqrtf(ssqH) * 0.08838834764831845f + 1e-8f);
        float sH = 127.0f / fmaxf(mmH * rdenH, 1e-5f);
        if (wh == 0 && (lane & 3) == 0) {
            s_c2[tokL] = (1.0f / sL) * dq2;
            s_c2[tokH] = (1.0f / sH) * dq2;
        }
        // quant + 16-bit packed stores straight into h1qT
        short* h1q16 = (short*)s_h1qT;
        #pragma unroll
        for (int nt = 0; nt < 4; nt++) {
            int j = wh * 32 + nt * 8 + 2 * (lane & 3);
            float sv0 = s_scale2[j], sv1 = s_scale2[j + 1];
            int g = j >> 2;
            int off = (j & 2) >> 1;
            float yl0 = sv0 * (hlo[nt][0] * rdenL), yl1 = sv1 * (hlo[nt][1] * rdenL);
            float yh0 = sv0 * (hhi[nt][0] * rdenH), yh1 = sv1 * (hhi[nt][1] * rdenH);
            h1q16[(g * 34 + tokL) * 2 + off] = pack_s8x2(yl0 * sL, yl1 * sL);
            h1q16[(g * 34 + tokH) * 2 + off] = pack_s8x2(yh0 * sH, yh1 * sH);
        }
    }
    BARH();   // h1qT + c2 ready for GEMM2

    // ---- GEMM2: this half's [16 x 64] dp4a (weights via L1/L2) ----
    const int tj2 = th & 15;
    const int j2 = tj2 * 4;
    const int tm2 = th >> 4;        // 0..7 -> token pair within half
    const int tok0 = half * 16 + tm2 * 2;
    int acc2[2][4];
    #pragma unroll
    for (int c = 0; c < 2; c++)
        #pragma unroll
        for (int j = 0; j < 4; j++) acc2[c][j] = 0;

    #pragma unroll 8
    for (int g = 0; g < G2; g++) {
        int2 a = *(const int2*)&s_h1qT[g * 34 + tok0];
        int4 w = *(const int4*)(g_wq2 + g * N2 + j2);
        acc2[0][0] = __dp4a(a.x, w.x, acc2[0][0]); acc2[0][1] = __dp4a(a.x, w.y, acc2[0][1]);
        acc2[0][2] = __dp4a(a.x, w.z, acc2[0][2]); acc2[0][3] = __dp4a(a.x, w.w, acc2[0][3]);
        acc2[1][0] = __dp4a(a.y, w.x, acc2[1][0]); acc2[1][1] = __dp4a(a.y, w.y, acc2[1][1]);
        acc2[1][2] = __dp4a(a.y, w.z, acc2[1][2]); acc2[1][3] = __dp4a(a.y, w.w, acc2[1][3]);
    }

    // ---- epilogue 2: RMSNorm(64) + quant (16-lane reduce; R14-identical) ----
    #pragma unroll
    for (int c = 0; c < 2; c++) {
        int tok = tok0 + c;
        float cf = s_c2[tok];
        float h[4];
        float ssq = 0.f;
        #pragma unroll
        for (int j = 0; j < 4; j++) {
            float v = fmaxf((float)acc2[c][j] * cf, 0.f);
            h[j] = v;
            ssq += v * v;
        }
        #pragma unroll
        for (int m = 1; m < 16; m <<= 1)
            ssq += __shfl_xor_sync(0xffffffffu, ssq, m);
        float denom = sqrtf(ssq) * 0.125f + 1e-8f;
        float rden = 1.0f / denom;
        float amx = 0.f;
        #pragma unroll
        for (int j = 0; j < 4; j++) {
            float y = s_scale3[j2 + j] * (h[j] * rden);
            h[j] = y;
            amx = fmaxf(amx, fabsf(y));
        }
        #pragma unroll
        for (int m = 1; m < 16; m <<= 1)
            amx = fmaxf(amx, __shfl_xor_sync(0xffffffffu, amx, m));
        float amc = fmaxf(amx, 1e-5f);
        float s = 127.0f / amc;
        if (tj2 == 0) s_c3[tok] = (1.0f / s) * dq3;
        s_h2q[tok * G3 + tj2] = pack_s8x4(h[0] * s, h[1] * s, h[2] * s, h[3] * s);
    }
    BARH();

    // ---- GEMM3: this half's [16 x 10], write output ----
    for (int p = th; p < 16 * N3; p += 128) {
        int l = p / N3, j = p % N3;
        int ltok = half * 16 + l;
        int a3 = 0;
        #pragma unroll
        for (int g = 0; g < G3; g++)
            a3 = __dp4a(s_h2q[ltok * G3 + g], g_wq3[j * G3 + g], a3);
        out[(blockIdx.x * MT + ltok) * N3 + j] = (float)a3 * s_c3[ltok];
    }
}

extern "C" void kernel_launch(void* const* d_in, const int* in_sizes, int n_in,
                              void* d_out, int out_size) {
    const float* x   = (const float*)d_in[0];
    const float* w1  = (const float*)d_in[1];
    const float* sc1 = (const float*)d_in[2];
    const float* w2  = (const float*)d_in[3];
    const float* sc2 = (const float*)d_in[4];
    const float* w3  = (const float*)d_in[5];
    const float* sc3 = (const float*)d_in[6];
    float* out = (float*)d_out;

    int ntok = in_sizes[0] / D1;   // 65536

    prep_partial<<<NPART, NT>>>(w1, w2, w3);
    prep_finalize<<<1, NT>>>(w2, w3);
    prep_quant_w1<<<(KC * NTILES * 32 * 2 + NT - 1) / NT, NT>>>(w1);
    ffn_main<<<ntok / MT, NT>>>(x, sc1, sc2, sc3, out);
}